// round 4
// baseline (speedup 1.0000x reference)
#include <cuda_runtime.h>
#include <cstdint>

#define T_TABLES 4
#define B_BATCH  8192
#define L_LEN    50
#define D_DIM    128
#define VOCAB_N  100000
#define ROWS_TOTAL (T_TABLES * B_BATCH)   // 32768

// Scratch (device globals: allocation-free rule)
__device__ float g_Wc[D_DIM * D_DIM];
__device__ float g_bc[D_DIM];

// ---------------------------------------------------------------------------
// Prep: Wc = W1^T W2^T W3^T (row i per block), bc = (b1 W2^T + b2) W3^T + b3.
// 128 blocks x 128 threads; block-local chaining via shared, no inter-block dep.
// ---------------------------------------------------------------------------
__global__ void prep_kernel(const float* __restrict__ W1, const float* __restrict__ b1,
                            const float* __restrict__ W2, const float* __restrict__ b2,
                            const float* __restrict__ W3, const float* __restrict__ b3) {
    __shared__ float s_col[D_DIM];
    __shared__ float s_w12[D_DIM];
    __shared__ float s_b12[D_DIM];
    const int i = blockIdx.x, j = threadIdx.x;

    s_col[j] = W1[j * D_DIM + i];                 // W1 column i
    __syncthreads();
    float s = 0.f;
#pragma unroll 8
    for (int k = 0; k < D_DIM; ++k) s += s_col[k] * W2[j * D_DIM + k];
    s_w12[j] = s;                                  // W12[i][j]
    __syncthreads();
    float s2 = 0.f;
#pragma unroll 8
    for (int m = 0; m < D_DIM; ++m) s2 += s_w12[m] * W3[j * D_DIM + m];
    g_Wc[i * D_DIM + j] = s2;

    if (i == 0) {
        float b = b2[j];
#pragma unroll 8
        for (int k = 0; k < D_DIM; ++k) b += b1[k] * W2[j * D_DIM + k];
        s_b12[j] = b;
        __syncthreads();
        float b2c = b3[j];
#pragma unroll 8
        for (int m = 0; m < D_DIM; ++m) b2c += s_b12[m] * W3[j * D_DIM + m];
        g_bc[j] = b2c;
    }
}

// ---------------------------------------------------------------------------
// Fused: each warp gathers+pools 4 rows, then applies the collapsed linear.
// GEMM FMA work interleaves (across warps) with gather load latency.
// grid = 1024 blocks x 256 threads (8 warps x 4 rows = 32 rows/block).
// ---------------------------------------------------------------------------
__global__ __launch_bounds__(256)
void fused_kernel(const int* __restrict__ indices,
                  const int* __restrict__ lengths,
                  const float* __restrict__ tables,
                  float* __restrict__ out) {
    __shared__ float sp[8 * 4 * D_DIM];            // 16 KB: per-warp pooled stage

    const int tid  = threadIdx.x;
    const int warp = tid >> 5, lane = tid & 31;
    const int row0 = (blockIdx.x * 8 + warp) * 4;
    float* my = sp + warp * 4 * D_DIM;

    const float4* WcV = (const float4*)g_Wc;
    const float4 bcv  = __ldg((const float4*)g_bc + lane);

    // ---- Phase A: gather + pool 4 rows (lane owns one float4 of D) ----
#pragma unroll 1
    for (int r = 0; r < 4; ++r) {
        const int g   = row0 + r;
        const int t   = g >> 13;                    // B = 8192
        const int len = lengths[g];
        const int* idxp = indices + (size_t)g * L_LEN;

        const int i_lo = idxp[lane];
        const int i_hi = (lane < (L_LEN - 32)) ? idxp[32 + lane] : 0;

        const float4* tab =
            (const float4*)tables + (size_t)t * ((size_t)VOCAB_N * (D_DIM / 4));

        float4 a0 = make_float4(0.f, 0.f, 0.f, 0.f);
        float4 a1 = a0, a2 = a0, a3 = a0;

        auto getidx = [&](int p) -> int {
            return (p < 32) ? __shfl_sync(0xffffffffu, i_lo, p)
                            : __shfl_sync(0xffffffffu, i_hi, p - 32);
        };

        int l = 0;
        for (; l + 3 < len; l += 4) {
            const int j0 = getidx(l + 0);
            const int j1 = getidx(l + 1);
            const int j2 = getidx(l + 2);
            const int j3 = getidx(l + 3);
            const float4 v0 = __ldg(&tab[(size_t)j0 * (D_DIM / 4) + lane]);
            const float4 v1 = __ldg(&tab[(size_t)j1 * (D_DIM / 4) + lane]);
            const float4 v2 = __ldg(&tab[(size_t)j2 * (D_DIM / 4) + lane]);
            const float4 v3 = __ldg(&tab[(size_t)j3 * (D_DIM / 4) + lane]);
            a0.x += v0.x; a0.y += v0.y; a0.z += v0.z; a0.w += v0.w;
            a1.x += v1.x; a1.y += v1.y; a1.z += v1.z; a1.w += v1.w;
            a2.x += v2.x; a2.y += v2.y; a2.z += v2.z; a2.w += v2.w;
            a3.x += v3.x; a3.y += v3.y; a3.z += v3.z; a3.w += v3.w;
        }
        for (; l < len; ++l) {
            const int j0 = getidx(l);
            const float4 v0 = __ldg(&tab[(size_t)j0 * (D_DIM / 4) + lane]);
            a0.x += v0.x; a0.y += v0.y; a0.z += v0.z; a0.w += v0.w;
        }

        float4 rs;
        rs.x = (a0.x + a1.x) + (a2.x + a3.x);
        rs.y = (a0.y + a1.y) + (a2.y + a3.y);
        rs.z = (a0.z + a1.z) + (a2.z + a3.z);
        rs.w = (a0.w + a1.w) + (a2.w + a3.w);
        *(float4*)&my[r * D_DIM + lane * 4] = rs;
    }
    __syncwarp();

    // ---- Phase B: out[r][:] = pooled[r][:] @ Wc + bc, 4 rows per warp ----
    float4 o0 = bcv, o1 = bcv, o2 = bcv, o3 = bcv;

#pragma unroll 4
    for (int d4 = 0; d4 < 32; ++d4) {
        // broadcast 4 pooled d-values per row via one LDS.128 each
        const float4 p0 = *(const float4*)&my[0 * D_DIM + d4 * 4];
        const float4 p1 = *(const float4*)&my[1 * D_DIM + d4 * 4];
        const float4 p2 = *(const float4*)&my[2 * D_DIM + d4 * 4];
        const float4 p3 = *(const float4*)&my[3 * D_DIM + d4 * 4];
        // Wc rows d4*4 .. d4*4+3, lane owns 4 output cols (L1-resident)
        const float4 w0 = __ldg(&WcV[(size_t)(d4 * 4 + 0) * (D_DIM / 4) + lane]);
        const float4 w1 = __ldg(&WcV[(size_t)(d4 * 4 + 1) * (D_DIM / 4) + lane]);
        const float4 w2 = __ldg(&WcV[(size_t)(d4 * 4 + 2) * (D_DIM / 4) + lane]);
        const float4 w3 = __ldg(&WcV[(size_t)(d4 * 4 + 3) * (D_DIM / 4) + lane]);

#define ACC(o, p)                                                         \
        o.x += p.x * w0.x + p.y * w1.x; o.x += p.z * w2.x + p.w * w3.x;   \
        o.y += p.x * w0.y + p.y * w1.y; o.y += p.z * w2.y + p.w * w3.y;   \
        o.z += p.x * w0.z + p.y * w1.z; o.z += p.z * w2.z + p.w * w3.z;   \
        o.w += p.x * w0.w + p.y * w1.w; o.w += p.z * w2.w + p.w * w3.w;
        ACC(o0, p0) ACC(o1, p1) ACC(o2, p2) ACC(o3, p3)
#undef ACC
    }

    *(float4*)(out + (size_t)(row0 + 0) * D_DIM + lane * 4) = o0;
    *(float4*)(out + (size_t)(row0 + 1) * D_DIM + lane * 4) = o1;
    *(float4*)(out + (size_t)(row0 + 2) * D_DIM + lane * 4) = o2;
    *(float4*)(out + (size_t)(row0 + 3) * D_DIM + lane * 4) = o3;
}

// ---------------------------------------------------------------------------
extern "C" void kernel_launch(void* const* d_in, const int* in_sizes, int n_in,
                              void* d_out, int out_size) {
    const int*   indices = (const int*)d_in[0];
    const int*   lengths = (const int*)d_in[1];
    const float* tables  = (const float*)d_in[2];
    const float* W1      = (const float*)d_in[3];
    const float* b1      = (const float*)d_in[4];
    const float* W2      = (const float*)d_in[5];
    const float* b2      = (const float*)d_in[6];
    const float* W3      = (const float*)d_in[7];
    const float* b3      = (const float*)d_in[8];
    float* out = (float*)d_out;

    prep_kernel<<<D_DIM, D_DIM>>>(W1, b1, W2, b2, W3, b3);
    fused_kernel<<<ROWS_TOTAL / 32, 256>>>(indices, lengths, tables, out);
}

// round 5
// speedup vs baseline: 1.2486x; 1.2486x over previous
#include <cuda_runtime.h>
#include <cstdint>

#define T_TABLES 4
#define B_BATCH  8192
#define L_LEN    50
#define D_DIM    128
#define VOCAB_N  100000
#define ROWS_TOTAL (T_TABLES * B_BATCH)   // 32768

// Scratch (device globals: allocation-free rule)
__device__ float g_M1[D_DIM * D_DIM];     // W2 @ W1
__device__ float g_b12[D_DIM];            // b1 @ W2^T + b2
__device__ float g_Wc[D_DIM * D_DIM];     // (W3 W2 W1)^T  -> out = pooled @ Wc
__device__ float g_bc[D_DIM];

// ---- f32x2 packed helpers -------------------------------------------------
__device__ __forceinline__ void fma2(unsigned long long& d,
                                     unsigned long long a, unsigned long long b) {
    asm("fma.rn.f32x2 %0, %1, %2, %0;" : "+l"(d) : "l"(a), "l"(b));
}
__device__ __forceinline__ unsigned long long add2(unsigned long long a,
                                                   unsigned long long b) {
    unsigned long long r;
    asm("add.rn.f32x2 %0, %1, %2;" : "=l"(r) : "l"(a), "l"(b));
    return r;
}
__device__ __forceinline__ float2 upk(unsigned long long v) {
    float2 r;
    asm("mov.b64 {%0, %1}, %2;" : "=f"(r.x), "=f"(r.y) : "l"(v));
    return r;
}

// ---------------------------------------------------------------------------
// prep1: blocks 0..127: M1[a][b] = sum_k W2[a][k] * W1[k][b]   (coalesced)
//        block 128:     b12[j]   = b2[j] + sum_k b1[k] * W2[j][k]
// ---------------------------------------------------------------------------
__global__ void prep1_kernel(const float* __restrict__ W1, const float* __restrict__ b1,
                             const float* __restrict__ W2, const float* __restrict__ b2) {
    __shared__ float rowA[D_DIM];
    const int tid = threadIdx.x;
    if (blockIdx.x < D_DIM) {
        const int a = blockIdx.x;
        rowA[tid] = W2[a * D_DIM + tid];
        __syncthreads();
        float s = 0.f;
#pragma unroll 8
        for (int k = 0; k < D_DIM; ++k) s += rowA[k] * W1[k * D_DIM + tid];
        g_M1[a * D_DIM + tid] = s;
    } else {
        const int warp = tid >> 5, lane = tid & 31;
        const float4 bv = *(const float4*)&b1[lane * 4];
#pragma unroll 1
        for (int jj = 0; jj < 32; ++jj) {
            const int j = warp * 32 + jj;
            const float4 wv = *(const float4*)&W2[j * D_DIM + lane * 4];
            float s = wv.x * bv.x + wv.y * bv.y + wv.z * bv.z + wv.w * bv.w;
#pragma unroll
            for (int o = 16; o; o >>= 1) s += __shfl_down_sync(0xffffffffu, s, o);
            if (lane == 0) g_b12[j] = s + b2[j];
        }
    }
}

// ---------------------------------------------------------------------------
// prep2: blocks 0..127: m[b] = sum_k W3[a][k] * M1[k][b]; Wc[b][a] = m[b]
//        block 128:     bc[j] = b3[j] + sum_k b12[k] * W3[j][k]
// ---------------------------------------------------------------------------
__global__ void prep2_kernel(const float* __restrict__ W3, const float* __restrict__ b3) {
    __shared__ float rowA[D_DIM];
    const int tid = threadIdx.x;
    if (blockIdx.x < D_DIM) {
        const int a = blockIdx.x;
        rowA[tid] = W3[a * D_DIM + tid];
        __syncthreads();
        float s = 0.f;
#pragma unroll 8
        for (int k = 0; k < D_DIM; ++k) s += rowA[k] * g_M1[k * D_DIM + tid];
        g_Wc[tid * D_DIM + a] = s;     // transposed store (one-shot, cheap)
    } else {
        const int warp = tid >> 5, lane = tid & 31;
        const float4 bv = *(const float4*)&g_b12[lane * 4];
#pragma unroll 1
        for (int jj = 0; jj < 32; ++jj) {
            const int j = warp * 32 + jj;
            const float4 wv = *(const float4*)&W3[j * D_DIM + lane * 4];
            float s = wv.x * bv.x + wv.y * bv.y + wv.z * bv.z + wv.w * bv.w;
#pragma unroll
            for (int o = 16; o; o >>= 1) s += __shfl_down_sync(0xffffffffu, s, o);
            if (lane == 0) g_bc[j] = s + b3[j];
        }
    }
}

// ---------------------------------------------------------------------------
// Fused: each warp gathers+pools 4 rows (dup-pair smem layout), then applies
// the collapsed linear with packed f32x2 FMAs.
// grid = 1024 blocks x 256 threads.
// ---------------------------------------------------------------------------
__global__ __launch_bounds__(256)
void fused_kernel(const int* __restrict__ indices,
                  const int* __restrict__ lengths,
                  const float* __restrict__ tables,
                  float* __restrict__ out) {
    __shared__ float sp[8 * 4 * 2 * D_DIM];        // 32 KB: per-warp duplicated pooled

    const int tid  = threadIdx.x;
    const int warp = tid >> 5, lane = tid & 31;
    const int row0 = (blockIdx.x * 8 + warp) * 4;
    float* my = sp + warp * 4 * 2 * D_DIM;         // 4 rows x 256 floats (dup pairs)

    // ---- Phase A: gather + pool 4 rows (lane owns one float4 of D) ----
#pragma unroll 1
    for (int r = 0; r < 4; ++r) {
        const int g   = row0 + r;
        const int t   = g >> 13;                    // B = 8192
        const int len = lengths[g];
        const int* idxp = indices + (size_t)g * L_LEN;

        const int i_lo = idxp[lane];
        const int i_hi = (lane < (L_LEN - 32)) ? idxp[32 + lane] : 0;

        const float4* tab =
            (const float4*)tables + (size_t)t * ((size_t)VOCAB_N * (D_DIM / 4));

        ulonglong2 A0 = {0ull, 0ull}, A1 = A0, A2 = A0, A3 = A0;

        auto getidx = [&](int p) -> int {
            return (p < 32) ? __shfl_sync(0xffffffffu, i_lo, p)
                            : __shfl_sync(0xffffffffu, i_hi, p - 32);
        };

        int l = 0;
        for (; l + 3 < len; l += 4) {
            const int j0 = getidx(l + 0);
            const int j1 = getidx(l + 1);
            const int j2 = getidx(l + 2);
            const int j3 = getidx(l + 3);
            const ulonglong2 v0 = __ldg((const ulonglong2*)(tab + (size_t)j0 * 32 + lane));
            const ulonglong2 v1 = __ldg((const ulonglong2*)(tab + (size_t)j1 * 32 + lane));
            const ulonglong2 v2 = __ldg((const ulonglong2*)(tab + (size_t)j2 * 32 + lane));
            const ulonglong2 v3 = __ldg((const ulonglong2*)(tab + (size_t)j3 * 32 + lane));
            A0.x = add2(A0.x, v0.x); A0.y = add2(A0.y, v0.y);
            A1.x = add2(A1.x, v1.x); A1.y = add2(A1.y, v1.y);
            A2.x = add2(A2.x, v2.x); A2.y = add2(A2.y, v2.y);
            A3.x = add2(A3.x, v3.x); A3.y = add2(A3.y, v3.y);
        }
        for (; l < len; ++l) {
            const int j0 = getidx(l);
            const ulonglong2 v0 = __ldg((const ulonglong2*)(tab + (size_t)j0 * 32 + lane));
            A0.x = add2(A0.x, v0.x); A0.y = add2(A0.y, v0.y);
        }

        const unsigned long long rlo = add2(add2(A0.x, A1.x), add2(A2.x, A3.x));
        const unsigned long long rhi = add2(add2(A0.y, A1.y), add2(A2.y, A3.y));
        const float2 f0 = upk(rlo);     // (p[c], p[c+1])   c = lane*4
        const float2 f1 = upk(rhi);     // (p[c+2], p[c+3])

        // duplicated-pair layout: pos 2d, 2d+1 both hold p[d]
        float4 s0, s1;
        s0.x = f0.x; s0.y = f0.x; s0.z = f0.y; s0.w = f0.y;
        s1.x = f1.x; s1.y = f1.x; s1.z = f1.y; s1.w = f1.y;
        *(float4*)&my[r * 2 * D_DIM + lane * 8]     = s0;
        *(float4*)&my[r * 2 * D_DIM + lane * 8 + 4] = s1;
    }
    __syncwarp();

    // ---- Phase B: out[r][:] = pooled[r][:] @ Wc + bc  (packed f32x2) ----
    const ulonglong2 bc2 = __ldg((const ulonglong2*)g_bc + lane);
    unsigned long long olo[4], ohi[4];
#pragma unroll
    for (int r = 0; r < 4; ++r) { olo[r] = bc2.x; ohi[r] = bc2.y; }

    const ulonglong2* WcU = (const ulonglong2*)g_Wc;   // row d: 32 x ulonglong2

#pragma unroll 4
    for (int d4 = 0; d4 < 32; ++d4) {
        const ulonglong2 w0 = __ldg(&WcU[(size_t)(d4 * 4 + 0) * 32 + lane]);
        const ulonglong2 w1 = __ldg(&WcU[(size_t)(d4 * 4 + 1) * 32 + lane]);
        const ulonglong2 w2 = __ldg(&WcU[(size_t)(d4 * 4 + 2) * 32 + lane]);
        const ulonglong2 w3 = __ldg(&WcU[(size_t)(d4 * 4 + 3) * 32 + lane]);
#pragma unroll
        for (int r = 0; r < 4; ++r) {
            const ulonglong2 q0 = *(const ulonglong2*)&my[r * 2 * D_DIM + d4 * 8];
            const ulonglong2 q1 = *(const ulonglong2*)&my[r * 2 * D_DIM + d4 * 8 + 4];
            fma2(olo[r], q0.x, w0.x); fma2(ohi[r], q0.x, w0.y);
            fma2(olo[r], q0.y, w1.x); fma2(ohi[r], q0.y, w1.y);
            fma2(olo[r], q1.x, w2.x); fma2(ohi[r], q1.x, w2.y);
            fma2(olo[r], q1.y, w3.x); fma2(ohi[r], q1.y, w3.y);
        }
    }

#pragma unroll
    for (int r = 0; r < 4; ++r) {
        ulonglong2 res; res.x = olo[r]; res.y = ohi[r];
        *(ulonglong2*)(out + (size_t)(row0 + r) * D_DIM + lane * 4) = res;
    }
}

// ---------------------------------------------------------------------------
extern "C" void kernel_launch(void* const* d_in, const int* in_sizes, int n_in,
                              void* d_out, int out_size) {
    const int*   indices = (const int*)d_in[0];
    const int*   lengths = (const int*)d_in[1];
    const float* tables  = (const float*)d_in[2];
    const float* W1      = (const float*)d_in[3];
    const float* b1      = (const float*)d_in[4];
    const float* W2      = (const float*)d_in[5];
    const float* b2      = (const float*)d_in[6];
    const float* W3      = (const float*)d_in[7];
    const float* b3      = (const float*)d_in[8];
    float* out = (float*)d_out;

    prep1_kernel<<<D_DIM + 1, D_DIM>>>(W1, b1, W2, b2);
    prep2_kernel<<<D_DIM + 1, D_DIM>>>(W3, b3);
    fused_kernel<<<ROWS_TOTAL / 32, 256>>>(indices, lengths, tables, out);
}